// round 8
// baseline (speedup 1.0000x reference)
#include <cuda_runtime.h>
#include <cstdint>

#define N_CELLS_MAX 50048
#define N_EDGES_MAX 1600512
#define C 64
#define SCAN_B 512

// Scratch (allocation-free rule: __device__ globals)
__device__ float g_msg[N_CELLS_MAX * C];
__device__ float g_as[N_CELLS_MAX];
__device__ float g_ad[N_CELLS_MAX];
__device__ float g_rowsum[N_CELLS_MAX];
__device__ float g_e[N_EDGES_MAX];
__device__ int   g_deg[N_CELLS_MAX];
__device__ int   g_rowstart[N_CELLS_MAX + 1];
__device__ int   g_cursor[N_CELLS_MAX];
__device__ int   g_blockpart[256];
__device__ int2  g_csr[N_EDGES_MAX];   // (dst, bitcast coef)

// ---------------------------------------------------------------------------
// K1: msg = x @ W ; alpha via the EXACT R1/R6/R7 fmaf+shfl sequence per row.
// 8 rows per warp (W LDS amortized 8x). UNCHANGED from R7 (passing).
// ---------------------------------------------------------------------------
__global__ void __launch_bounds__(256) k_gemm_alpha(
    const float* __restrict__ x, const float* __restrict__ W,
    const float* __restrict__ a, int n)
{
    __shared__ float Ws[C * C];
    __shared__ float As[2 * C];
    int tid = threadIdx.x;
    for (int i = tid; i < C * C; i += blockDim.x) Ws[i] = W[i];
    if (tid < 2 * C) As[tid] = a[tid];
    __syncthreads();

    int warp = tid >> 5, lane = tid & 31;
    int row0 = (blockIdx.x * 8 + warp) * 8;
    if (row0 >= n) return;

    float xr0[8], xr1[8];
    #pragma unroll
    for (int r = 0; r < 8; r++) {
        int row = row0 + r;
        if (row < n) {
            const float* xr = x + (size_t)row * C;
            xr0[r] = xr[lane];
            xr1[r] = xr[lane + 32];
        } else {
            xr0[r] = 0.f;
            xr1[r] = 0.f;
        }
    }

    float acc0[8], acc1[8];
    #pragma unroll
    for (int r = 0; r < 8; r++) { acc0[r] = 0.f; acc1[r] = 0.f; }

    #pragma unroll
    for (int k = 0; k < 32; k++) {
        float w0 = Ws[k * C + lane];
        float w1 = Ws[k * C + lane + 32];
        #pragma unroll
        for (int r = 0; r < 8; r++) {
            float xv = __shfl_sync(0xffffffffu, xr0[r], k);
            acc0[r] = fmaf(xv, w0, acc0[r]);
            acc1[r] = fmaf(xv, w1, acc1[r]);
        }
    }
    #pragma unroll
    for (int k = 0; k < 32; k++) {
        float w0 = Ws[(k + 32) * C + lane];
        float w1 = Ws[(k + 32) * C + lane + 32];
        #pragma unroll
        for (int r = 0; r < 8; r++) {
            float xv = __shfl_sync(0xffffffffu, xr1[r], k);
            acc0[r] = fmaf(xv, w0, acc0[r]);
            acc1[r] = fmaf(xv, w1, acc1[r]);
        }
    }

    #pragma unroll
    for (int r = 0; r < 8; r++) {
        int row = row0 + r;
        bool ok = (row < n);
        if (ok) {
            g_msg[(size_t)row * C + lane]      = acc0[r];
            g_msg[(size_t)row * C + lane + 32] = acc1[r];
        }
        float s0 = acc0[r] * As[lane]     + acc1[r] * As[lane + 32];
        float s1 = acc0[r] * As[C + lane] + acc1[r] * As[C + lane + 32];
        #pragma unroll
        for (int o = 16; o > 0; o >>= 1) {
            s0 += __shfl_xor_sync(0xffffffffu, s0, o);
            s1 += __shfl_xor_sync(0xffffffffu, s1, o);
        }
        if (lane == 0 && ok) {
            g_as[row] = s0;
            g_ad[row] = s1;
            g_rowsum[row] = 0.f;
            g_deg[row] = 0;
        }
    }
}

// ---------------------------------------------------------------------------
// K2: e = LeakyReLU(as[src] + ad[dst]); store e; rowsum[src] += e; deg[src]++
// UNCHANGED scalar form (identical float values to all passing rounds).
// ---------------------------------------------------------------------------
__global__ void __launch_bounds__(256) k_edge_e(
    const int* __restrict__ src, const int* __restrict__ dst, int E)
{
    int i = blockIdx.x * blockDim.x + threadIdx.x;
    if (i >= E) return;
    int s = src[i], d = dst[i];
    float v = g_as[s] + g_ad[d];
    float e = v > 0.f ? v : 0.2f * v;
    g_e[i] = e;
    atomicAdd(&g_rowsum[s], e);
    atomicAdd(&g_deg[s], 1);
}

// ---------------------------------------------------------------------------
// Exclusive prefix scan of g_deg -> g_rowstart, g_cursor
// ---------------------------------------------------------------------------
__global__ void __launch_bounds__(SCAN_B) k_scan1(int n)
{
    __shared__ int sh[SCAN_B];
    int t = threadIdx.x;
    int gid = blockIdx.x * SCAN_B + t;
    sh[t] = (gid < n) ? g_deg[gid] : 0;
    __syncthreads();
    for (int o = SCAN_B / 2; o > 0; o >>= 1) {
        if (t < o) sh[t] += sh[t + o];
        __syncthreads();
    }
    if (t == 0) g_blockpart[blockIdx.x] = sh[0];
}

// Parallel exclusive scan over block partials (nb <= 256). Was a serial
// 1-thread loop costing 8.5us; now a 256-thread Hillis-Steele (~1us).
__global__ void __launch_bounds__(256) k_scan2(int nb)
{
    __shared__ int sh[256];
    int t = threadIdx.x;
    int v = (t < nb) ? g_blockpart[t] : 0;
    sh[t] = v;
    __syncthreads();
    #pragma unroll
    for (int o = 1; o < 256; o <<= 1) {
        int xv = (t >= o) ? sh[t - o] : 0;
        __syncthreads();
        sh[t] += xv;
        __syncthreads();
    }
    if (t < nb) g_blockpart[t] = sh[t] - v;   // exclusive
}

__global__ void __launch_bounds__(SCAN_B) k_scan3(int n)
{
    __shared__ int sh[SCAN_B];
    int t = threadIdx.x;
    int gid = blockIdx.x * SCAN_B + t;
    int v = (gid < n) ? g_deg[gid] : 0;
    sh[t] = v;
    __syncthreads();
    for (int o = 1; o < SCAN_B; o <<= 1) {
        int xv = (t >= o) ? sh[t - o] : 0;
        __syncthreads();
        sh[t] += xv;
        __syncthreads();
    }
    int excl = sh[t] - v + g_blockpart[blockIdx.x];
    if (gid < n) {
        g_rowstart[gid] = excl;
        g_cursor[gid]   = excl;
        if (gid == n - 1) g_rowstart[n] = excl + v;
    }
}

// ---------------------------------------------------------------------------
// Build CSR with precomputed coef (IDENTICAL expression to R6/R7 K3:
// g_e[e] / g_rowsum[s] * ev[e]). Vectorized 4 edges/thread — only CSR
// ordering changes, which the fp64 output sum is insensitive to.
// ---------------------------------------------------------------------------
__global__ void __launch_bounds__(256) k_build(
    const int* __restrict__ src, const int* __restrict__ dst,
    const float* __restrict__ ev, int E)
{
    int i = (blockIdx.x * blockDim.x + threadIdx.x) * 4;
    if (i >= E) return;
    if (i + 3 < E) {
        int4 s = *(const int4*)(src + i);
        int4 d = *(const int4*)(dst + i);
        float4 v = *(const float4*)(ev + i);
        float4 e = *(const float4*)(g_e + i);
        float c0 = e.x / g_rowsum[s.x] * v.x;
        float c1 = e.y / g_rowsum[s.y] * v.y;
        float c2 = e.z / g_rowsum[s.z] * v.z;
        float c3 = e.w / g_rowsum[s.w] * v.w;
        int p0 = atomicAdd(&g_cursor[s.x], 1);
        int p1 = atomicAdd(&g_cursor[s.y], 1);
        int p2 = atomicAdd(&g_cursor[s.z], 1);
        int p3 = atomicAdd(&g_cursor[s.w], 1);
        g_csr[p0] = make_int2(d.x, __float_as_int(c0));
        g_csr[p1] = make_int2(d.y, __float_as_int(c1));
        g_csr[p2] = make_int2(d.z, __float_as_int(c2));
        g_csr[p3] = make_int2(d.w, __float_as_int(c3));
    } else {
        for (int e = i; e < E; e++) {
            int s = src[e];
            float coef = g_e[e] / g_rowsum[s] * ev[e];
            int p = atomicAdd(&g_cursor[s], 1);
            g_csr[p] = make_int2(dst[e], __float_as_int(coef));
        }
    }
}

// ---------------------------------------------------------------------------
// K3: one warp per row: out[row] = sum_i coef_i * msg[dst_i].
// Products rounded to fp32 (matching the reference's vals*msg rounding),
// summed in fp64 registers -> output independent of CSR ordering.
// ---------------------------------------------------------------------------
__global__ void __launch_bounds__(256) k_row_aggregate(float* __restrict__ out, int n)
{
    int wid = threadIdx.x >> 5, lane = threadIdx.x & 31;
    int row = blockIdx.x * 8 + wid;
    if (row >= n) return;

    int beg = g_rowstart[row];
    int end = g_rowstart[row + 1];

    double a0 = 0.0, a1 = 0.0;
    int i = beg;
    for (; i + 4 <= end; i += 4) {
        int2 p0 = g_csr[i];
        int2 p1 = g_csr[i + 1];
        int2 p2 = g_csr[i + 2];
        int2 p3 = g_csr[i + 3];
        float2 m0 = *(const float2*)&g_msg[(size_t)p0.x * C + lane * 2];
        float2 m1 = *(const float2*)&g_msg[(size_t)p1.x * C + lane * 2];
        float2 m2 = *(const float2*)&g_msg[(size_t)p2.x * C + lane * 2];
        float2 m3 = *(const float2*)&g_msg[(size_t)p3.x * C + lane * 2];
        float c0 = __int_as_float(p0.y);
        float c1 = __int_as_float(p1.y);
        float c2 = __int_as_float(p2.y);
        float c3 = __int_as_float(p3.y);
        a0 += (double)(c0 * m0.x); a1 += (double)(c0 * m0.y);
        a0 += (double)(c1 * m1.x); a1 += (double)(c1 * m1.y);
        a0 += (double)(c2 * m2.x); a1 += (double)(c2 * m2.y);
        a0 += (double)(c3 * m3.x); a1 += (double)(c3 * m3.y);
    }
    for (; i < end; i++) {
        int2 p = g_csr[i];
        float2 m = *(const float2*)&g_msg[(size_t)p.x * C + lane * 2];
        float c = __int_as_float(p.y);
        a0 += (double)(c * m.x);
        a1 += (double)(c * m.y);
    }
    *(float2*)&out[(size_t)row * C + lane * 2] = make_float2((float)a0, (float)a1);
}

extern "C" void kernel_launch(void* const* d_in, const int* in_sizes, int n_in,
                              void* d_out, int out_size)
{
    const float* x_source   = (const float*)d_in[0];   // [n, 64]
    const int*   edge_index = (const int*)d_in[1];     // [2, E]
    const float* edge_vals  = (const float*)d_in[2];   // [E]
    const float* W          = (const float*)d_in[3];   // [64, 64]
    const float* a          = (const float*)d_in[4];   // [128]
    float* out = (float*)d_out;

    int n = in_sizes[0] / C;
    int E = in_sizes[2];
    const int* src = edge_index;
    const int* dst = edge_index + E;

    // K1: 8 rows/warp, 8 warps -> 64 rows per block
    int blocks1 = (n + 63) / 64;
    k_gemm_alpha<<<blocks1, 256>>>(x_source, W, a, n);

    // K2: one thread/edge (identical to passing rounds)
    int blocks2 = (E + 255) / 256;
    k_edge_e<<<blocks2, 256>>>(src, dst, E);

    // CSR build
    int nb = (n + SCAN_B - 1) / SCAN_B;
    k_scan1<<<nb, SCAN_B>>>(n);
    k_scan2<<<1, 256>>>(nb);
    k_scan3<<<nb, SCAN_B>>>(n);
    int blocksB = (E + 4 * 256 - 1) / (4 * 256);
    k_build<<<blocksB, 256>>>(src, dst, edge_vals, E);

    // K3: one warp per row
    int blocks3 = (n + 7) / 8;
    k_row_aggregate<<<blocks3, 256>>>(out, n);
}

// round 9
// speedup vs baseline: 1.0680x; 1.0680x over previous
#include <cuda_runtime.h>
#include <cstdint>

#define N_CELLS_MAX 50048
#define N_EDGES_MAX 1600512
#define C 64
#define SCAN_B 512

// Scratch (allocation-free rule: __device__ globals)
__device__ float g_msg[N_CELLS_MAX * C];
__device__ float g_as[N_CELLS_MAX];
__device__ float g_ad[N_CELLS_MAX];
__device__ float g_rowsum[N_CELLS_MAX];
__device__ float g_e[N_EDGES_MAX];
__device__ int   g_deg[N_CELLS_MAX];
__device__ int   g_rowstart[N_CELLS_MAX + 1];
__device__ int   g_cursor[N_CELLS_MAX];
__device__ int   g_blockpart[128];
__device__ int2  g_csr[N_EDGES_MAX];   // (dst, bitcast coef)

// ---------------------------------------------------------------------------
// K1: msg = x @ W ; alpha via the EXACT R1/R6/R7 fmaf+shfl sequence per row.
// 8 rows per warp. UNCHANGED from R7/R8 (passing).
// ---------------------------------------------------------------------------
__global__ void __launch_bounds__(256) k_gemm_alpha(
    const float* __restrict__ x, const float* __restrict__ W,
    const float* __restrict__ a, int n)
{
    __shared__ float Ws[C * C];
    __shared__ float As[2 * C];
    int tid = threadIdx.x;
    for (int i = tid; i < C * C; i += blockDim.x) Ws[i] = W[i];
    if (tid < 2 * C) As[tid] = a[tid];
    __syncthreads();

    int warp = tid >> 5, lane = tid & 31;
    int row0 = (blockIdx.x * 8 + warp) * 8;
    if (row0 >= n) return;

    float xr0[8], xr1[8];
    #pragma unroll
    for (int r = 0; r < 8; r++) {
        int row = row0 + r;
        if (row < n) {
            const float* xr = x + (size_t)row * C;
            xr0[r] = xr[lane];
            xr1[r] = xr[lane + 32];
        } else {
            xr0[r] = 0.f;
            xr1[r] = 0.f;
        }
    }

    float acc0[8], acc1[8];
    #pragma unroll
    for (int r = 0; r < 8; r++) { acc0[r] = 0.f; acc1[r] = 0.f; }

    #pragma unroll
    for (int k = 0; k < 32; k++) {
        float w0 = Ws[k * C + lane];
        float w1 = Ws[k * C + lane + 32];
        #pragma unroll
        for (int r = 0; r < 8; r++) {
            float xv = __shfl_sync(0xffffffffu, xr0[r], k);
            acc0[r] = fmaf(xv, w0, acc0[r]);
            acc1[r] = fmaf(xv, w1, acc1[r]);
        }
    }
    #pragma unroll
    for (int k = 0; k < 32; k++) {
        float w0 = Ws[(k + 32) * C + lane];
        float w1 = Ws[(k + 32) * C + lane + 32];
        #pragma unroll
        for (int r = 0; r < 8; r++) {
            float xv = __shfl_sync(0xffffffffu, xr1[r], k);
            acc0[r] = fmaf(xv, w0, acc0[r]);
            acc1[r] = fmaf(xv, w1, acc1[r]);
        }
    }

    #pragma unroll
    for (int r = 0; r < 8; r++) {
        int row = row0 + r;
        bool ok = (row < n);
        if (ok) {
            g_msg[(size_t)row * C + lane]      = acc0[r];
            g_msg[(size_t)row * C + lane + 32] = acc1[r];
        }
        float s0 = acc0[r] * As[lane]     + acc1[r] * As[lane + 32];
        float s1 = acc0[r] * As[C + lane] + acc1[r] * As[C + lane + 32];
        #pragma unroll
        for (int o = 16; o > 0; o >>= 1) {
            s0 += __shfl_xor_sync(0xffffffffu, s0, o);
            s1 += __shfl_xor_sync(0xffffffffu, s1, o);
        }
        if (lane == 0 && ok) {
            g_as[row] = s0;
            g_ad[row] = s1;
            g_rowsum[row] = 0.f;
            g_deg[row] = 0;
        }
    }
}

// ---------------------------------------------------------------------------
// K2: UNCHANGED from R7/R8 (measured 6.58e-4 / 6.60e-4 — repeatable point).
// ---------------------------------------------------------------------------
__global__ void __launch_bounds__(256) k_edge_e(
    const int* __restrict__ src, const int* __restrict__ dst, int E)
{
    int i = blockIdx.x * blockDim.x + threadIdx.x;
    if (i >= E) return;
    int s = src[i], d = dst[i];
    float v = g_as[s] + g_ad[d];
    float e = v > 0.f ? v : 0.2f * v;
    g_e[i] = e;
    atomicAdd(&g_rowsum[s], e);
    atomicAdd(&g_deg[s], 1);
}

// ---------------------------------------------------------------------------
// Scan stage 1: per-block sums of g_deg (nb = ceil(n/512) <= 98 blocks)
// ---------------------------------------------------------------------------
__global__ void __launch_bounds__(SCAN_B) k_scan1(int n)
{
    __shared__ int sh[SCAN_B];
    int t = threadIdx.x;
    int gid = blockIdx.x * SCAN_B + t;
    sh[t] = (gid < n) ? g_deg[gid] : 0;
    __syncthreads();
    for (int o = SCAN_B / 2; o > 0; o >>= 1) {
        if (t < o) sh[t] += sh[t + o];
        __syncthreads();
    }
    if (t == 0) g_blockpart[blockIdx.x] = sh[0];
}

// ---------------------------------------------------------------------------
// Scan stage 2+3 fused: each block redundantly scans the <=128 block partials
// in smem (cheap), then does its local exclusive scan of g_deg and writes
// rowstart/cursor. Removes the separate k_scan2 launch (4.4us overhead).
// ---------------------------------------------------------------------------
__global__ void __launch_bounds__(SCAN_B) k_scan3(int n, int nb)
{
    __shared__ int part[128];
    __shared__ int sh[SCAN_B];
    int t = threadIdx.x;

    if (t < 128) part[t] = (t < nb) ? g_blockpart[t] : 0;
    __syncthreads();
    #pragma unroll
    for (int o = 1; o < 128; o <<= 1) {
        int xv = (t < 128 && t >= o) ? part[t - o] : 0;
        __syncthreads();
        if (t < 128) part[t] += xv;         // inclusive scan of partials
        __syncthreads();
    }
    int base = (blockIdx.x == 0) ? 0 : part[blockIdx.x - 1];

    int gid = blockIdx.x * SCAN_B + t;
    int v = (gid < n) ? g_deg[gid] : 0;
    sh[t] = v;
    __syncthreads();
    for (int o = 1; o < SCAN_B; o <<= 1) {
        int xv = (t >= o) ? sh[t - o] : 0;
        __syncthreads();
        sh[t] += xv;
        __syncthreads();
    }
    int excl = sh[t] - v + base;
    if (gid < n) {
        g_rowstart[gid] = excl;
        g_cursor[gid]   = excl;
        if (gid == n - 1) g_rowstart[n] = excl + v;
    }
}

// ---------------------------------------------------------------------------
// Build CSR with precomputed coef (IDENTICAL expression to R6/R7/R8).
// 4 edges per thread.
// ---------------------------------------------------------------------------
__global__ void __launch_bounds__(256) k_build(
    const int* __restrict__ src, const int* __restrict__ dst,
    const float* __restrict__ ev, int E)
{
    int i = (blockIdx.x * blockDim.x + threadIdx.x) * 4;
    if (i >= E) return;
    if (i + 3 < E) {
        int4 s = *(const int4*)(src + i);
        int4 d = *(const int4*)(dst + i);
        float4 v = *(const float4*)(ev + i);
        float4 e = *(const float4*)(g_e + i);
        float c0 = e.x / g_rowsum[s.x] * v.x;
        float c1 = e.y / g_rowsum[s.y] * v.y;
        float c2 = e.z / g_rowsum[s.z] * v.z;
        float c3 = e.w / g_rowsum[s.w] * v.w;
        int p0 = atomicAdd(&g_cursor[s.x], 1);
        int p1 = atomicAdd(&g_cursor[s.y], 1);
        int p2 = atomicAdd(&g_cursor[s.z], 1);
        int p3 = atomicAdd(&g_cursor[s.w], 1);
        g_csr[p0] = make_int2(d.x, __float_as_int(c0));
        g_csr[p1] = make_int2(d.y, __float_as_int(c1));
        g_csr[p2] = make_int2(d.z, __float_as_int(c2));
        g_csr[p3] = make_int2(d.w, __float_as_int(c3));
    } else {
        for (int e = i; e < E; e++) {
            int s = src[e];
            float coef = g_e[e] / g_rowsum[s] * ev[e];
            int p = atomicAdd(&g_cursor[s], 1);
            g_csr[p] = make_int2(dst[e], __float_as_int(coef));
        }
    }
}

// ---------------------------------------------------------------------------
// K3: one warp per row, fp32 fma accumulation (R7 form — measured pass).
// 8-way unroll for MLP; accumulator chain order identical to R7's sequential
// order (single dependence chain, i ascending).
// ---------------------------------------------------------------------------
__global__ void __launch_bounds__(256) k_row_aggregate(float* __restrict__ out, int n)
{
    int wid = threadIdx.x >> 5, lane = threadIdx.x & 31;
    int row = blockIdx.x * 8 + wid;
    if (row >= n) return;

    int beg = g_rowstart[row];
    int end = g_rowstart[row + 1];

    float a0 = 0.f, a1 = 0.f;
    int i = beg;
    for (; i + 8 <= end; i += 8) {
        int2 p[8];
        #pragma unroll
        for (int u = 0; u < 8; u++) p[u] = g_csr[i + u];
        float2 m[8];
        #pragma unroll
        for (int u = 0; u < 8; u++)
            m[u] = *(const float2*)&g_msg[(size_t)p[u].x * C + lane * 2];
        #pragma unroll
        for (int u = 0; u < 8; u++) {
            float c = __int_as_float(p[u].y);
            a0 = fmaf(c, m[u].x, a0);
            a1 = fmaf(c, m[u].y, a1);
        }
    }
    for (; i < end; i++) {
        int2 p = g_csr[i];
        float2 m = *(const float2*)&g_msg[(size_t)p.x * C + lane * 2];
        float c = __int_as_float(p.y);
        a0 = fmaf(c, m.x, a0);
        a1 = fmaf(c, m.y, a1);
    }
    *(float2*)&out[(size_t)row * C + lane * 2] = make_float2(a0, a1);
}

extern "C" void kernel_launch(void* const* d_in, const int* in_sizes, int n_in,
                              void* d_out, int out_size)
{
    const float* x_source   = (const float*)d_in[0];   // [n, 64]
    const int*   edge_index = (const int*)d_in[1];     // [2, E]
    const float* edge_vals  = (const float*)d_in[2];   // [E]
    const float* W          = (const float*)d_in[3];   // [64, 64]
    const float* a          = (const float*)d_in[4];   // [128]
    float* out = (float*)d_out;

    int n = in_sizes[0] / C;
    int E = in_sizes[2];
    const int* src = edge_index;
    const int* dst = edge_index + E;

    // K1: 8 rows/warp, 8 warps -> 64 rows per block
    int blocks1 = (n + 63) / 64;
    k_gemm_alpha<<<blocks1, 256>>>(x_source, W, a, n);

    // K2: one thread/edge (frozen)
    int blocks2 = (E + 255) / 256;
    k_edge_e<<<blocks2, 256>>>(src, dst, E);

    // CSR build (scan2 fused into scan3)
    int nb = (n + SCAN_B - 1) / SCAN_B;
    k_scan1<<<nb, SCAN_B>>>(n);
    k_scan3<<<nb, SCAN_B>>>(n, nb);
    int blocksB = (E + 4 * 256 - 1) / (4 * 256);
    k_build<<<blocksB, 256>>>(src, dst, edge_vals, E);

    // K3: one warp per row
    int blocks3 = (n + 7) / 8;
    k_row_aggregate<<<blocks3, 256>>>(out, n);
}